// round 1
// baseline (speedup 1.0000x reference)
#include <cuda_runtime.h>
#include <cuda_bf16.h>

// LRN spatial 5x5: out = x / (k + alpha * boxsum5x5(x^2))^beta
// x: (16, 96, 224, 224) fp32.  k=2, alpha=1e-4, beta=0.75, zero padding.
//
// Strategy: HBM-bound separable stencil.
//   Block = 16 output rows x 224 cols of one (n,c) plane (+2-row halo).
//   Phase A: coalesced float4 loads of 20 input rows -> padded shared xs.
//   Phase B: horizontal 5-tap sum of squares (register sliding window,
//            three aligned LDS.128 per 4 outputs -> conflict-free).
//   Phase C: vertical 5-tap running sum per column; x re-read from shared;
//            d^-0.75 = rsqrt(d) * sqrt(rsqrt(d))  (2 MUFU ops).

#define LRN_W 224
#define LRN_H 224
#define LRN_TH 16               // output rows per block
#define LRN_INR (LRN_TH + 4)    // input rows incl. halo = 20
#define LRN_PADL 4              // left pad in xs (keeps float4 stores aligned)
#define LRN_XSW 232             // 4 + 224 + 4

__global__ __launch_bounds__(256, 4)
void lrn_kernel(const float* __restrict__ x, float* __restrict__ out) {
    __shared__ float xs[LRN_INR][LRN_XSW];  // raw x, padded: global col c -> idx c+4
    __shared__ float hs[LRN_INR][LRN_W];    // horizontal 5-tap sum of squares

    const int plane = blockIdx.x;                 // 0..1535  (n*96 + c)
    const int r0    = blockIdx.y * LRN_TH;        // first output row
    const float* px = x   + (size_t)plane * (LRN_H * LRN_W);
    float*     pout = out + (size_t)plane * (LRN_H * LRN_W);
    const int tid = threadIdx.x;

    // ---------- Phase A: load input rows r0-2 .. r0+TH+1 (zero outside) ----------
    const int NG = LRN_INR * (LRN_W / 4);   // 20 * 56 = 1120 float4 groups
    #pragma unroll 2
    for (int g = tid; g < NG; g += 256) {
        int row = g / (LRN_W / 4);
        int c4  = (g % (LRN_W / 4)) * 4;
        int grow = r0 - 2 + row;
        float4 v = make_float4(0.f, 0.f, 0.f, 0.f);
        if (grow >= 0 && grow < LRN_H)
            v = *reinterpret_cast<const float4*>(px + grow * LRN_W + c4);
        *reinterpret_cast<float4*>(&xs[row][LRN_PADL + c4]) = v;
    }
    // zero pads: xs idx 2,3 (cols -2,-1) and 228,229 (cols 224,225)
    if (tid < LRN_INR * 4) {
        int row = tid >> 2;
        int j   = tid & 3;
        int idx = (j < 2) ? (2 + j) : (226 + j);   // 2,3,228,229
        xs[row][idx] = 0.f;
    }
    __syncthreads();

    // ---------- Phase B: horizontal 5-tap sum of squares ----------
    // out col c needs xs idx c+2 .. c+6. Group of 4 outputs c4..c4+3 needs
    // idx c4+2..c4+9 -> covered by 3 aligned float4 loads at c4, c4+4, c4+8.
    #pragma unroll 2
    for (int g = tid; g < NG; g += 256) {
        int row = g / (LRN_W / 4);
        int c4  = (g % (LRN_W / 4)) * 4;
        float4 a  = *reinterpret_cast<const float4*>(&xs[row][c4]);
        float4 b  = *reinterpret_cast<const float4*>(&xs[row][c4 + 4]);
        float4 cc = *reinterpret_cast<const float4*>(&xs[row][c4 + 8]);
        float q2 = a.z * a.z,  q3 = a.w * a.w;
        float q4 = b.x * b.x,  q5 = b.y * b.y;
        float q6 = b.z * b.z,  q7 = b.w * b.w;
        float q8 = cc.x * cc.x, q9 = cc.y * cc.y;
        float h0 = q2 + q3 + q4 + q5 + q6;
        float h1 = h0 - q2 + q7;
        float h2 = h1 - q3 + q8;
        float h3 = h2 - q4 + q9;
        *reinterpret_cast<float4*>(&hs[row][c4]) = make_float4(h0, h1, h2, h3);
    }
    __syncthreads();

    // ---------- Phase C: vertical 5-tap running sum + normalize ----------
    if (tid < LRN_W) {
        const int c = tid;
        float v = hs[0][c] + hs[1][c] + hs[2][c] + hs[3][c] + hs[4][c];
        #pragma unroll
        for (int i = 0; i < LRN_TH; i++) {
            float xv = xs[i + 2][LRN_PADL + c];
            float d  = 2.0f + 1e-4f * v;
            float r  = rsqrtf(d);            // d^-0.5
            float dn = r * sqrtf(r);         // d^-0.75
            pout[(r0 + i) * LRN_W + c] = xv * dn;
            if (i + 1 < LRN_TH)
                v += hs[i + 5][c] - hs[i][c];
        }
    }
}

extern "C" void kernel_launch(void* const* d_in, const int* in_sizes, int n_in,
                              void* d_out, int out_size) {
    const float* x = (const float*)d_in[0];
    float* out = (float*)d_out;
    (void)in_sizes; (void)n_in; (void)out_size;
    dim3 grid(16 * 96, LRN_H / LRN_TH);   // 1536 planes x 14 row-strips
    lrn_kernel<<<grid, 256>>>(x, out);
}